// round 8
// baseline (speedup 1.0000x reference)
#include <cuda_runtime.h>

// GlottalFlowTable — fixed shapes: B=32, S=524288, HOP=256, L=100, frames=2048
//
// R8: micro-tune of R7 (the measured optimum shape: 4 samples/thread,
// per-sample scalar-LDG bilinear gather).
//  - p2 incremental: one I2F + FMUL per thread instead of per sample
//  - wp loaded with default cache policy (L2-resident across graph replays;
//    R7 evidence: only 100MB of 128MB streamed hit HBM). out keeps __stcs
//    (write-once, no reuse).
//  - gather structure untouched — it sits at the L1TEX wavefront floor.

constexpr int B      = 32;
constexpr int S      = 524288;
constexpr int HOP    = 256;
constexpr int L      = 100;
constexpr int FRAMES = S / HOP;    // 2048
constexpr int TROWS  = FRAMES + 1; // 2049
constexpr int S4     = S / 4;      // 131072 float4 per batch row

__global__ __launch_bounds__(256)
void glottal_flow_kernel(const float* __restrict__ wp,
                         const float* __restrict__ tables,
                         float* __restrict__ out)
{
    int i4 = blockIdx.x * 256 + threadIdx.x;   // global float4 index
    int b  = i4 >> 17;                         // / S4 (131072)
    int s  = (i4 & (S4 - 1)) << 2;             // sample index within batch row
    int f  = s >> 8;                           // frame (HOP = 256)
    int t  = s & (HOP - 1);                    // position within frame

    float4 w = __ldg(reinterpret_cast<const float4*>(wp) + i4); // cached (L2 reuse)

    const float* rowF = tables + (size_t)(b * TROWS + f) * L; // floor frame row
    const float* rowC = rowF + L;                              // ceil frame row

    float wk[4] = {w.x, w.y, w.z, w.w};
    float r[4];

    float p2 = (float)t * (1.0f / (float)HOP);  // one I2F+FMUL per thread

#pragma unroll
    for (int k = 0; k < 4; ++k) {
        float idx_raw = wk[k] * (float)L;
        int   fi      = (int)idx_raw;              // trunc toward zero (data >= 0)
        fi            = max(0, min(fi, L - 1));    // clip like reference
        float p       = idx_raw - (float)fi;
        int   fj      = fi + 1;
        if (fj == L) fj = 0;                       // padded column L == column 0

        float loF = __ldg(rowF + fi);
        float hiF = __ldg(rowF + fj);
        float loC = __ldg(rowC + fi);
        float hiC = __ldg(rowC + fj);

        float vF = fmaf(p, hiF - loF, loF);        // phase lerp, floor frame
        float vC = fmaf(p, hiC - loC, loC);        // phase lerp, ceil frame
        r[k] = fmaf(p2, vC - vF, vF);              // frame lerp
        p2 += (1.0f / (float)HOP);                 // incremental p2
    }

    __stcs(reinterpret_cast<float4*>(out) + i4,    // streaming store (no reuse)
           make_float4(r[0], r[1], r[2], r[3]));
}

extern "C" void kernel_launch(void* const* d_in, const int* in_sizes, int n_in,
                              void* d_out, int out_size)
{
    const float* wp     = (const float*)d_in[0];
    const float* tables = (const float*)d_in[1];
    float*       out    = (float*)d_out;

    constexpr int total4 = (B * S) / 4;            // 4,194,304 float4 work items
    glottal_flow_kernel<<<total4 / 256, 256>>>(wp, tables, out);
}

// round 9
// speedup vs baseline: 1.2051x; 1.2051x over previous
#include <cuda_runtime.h>

// GlottalFlowTable — fixed shapes: B=32, S=524288, HOP=256, L=100, frames=2048
//
// R9: consolidation — exact R7, the measured optimum (kernel 29.4us).
// R8's two deltas both regressed and are reverted:
//   - p2 computed independently per k (ILP; incremental FADD chain was serial)
//   - wp loaded with __ldcs (streaming; cached __ldg raised DRAM%)
// The kernel sits at a joint L1TEX-wavefront / LSU-issue / DRAM plateau
// (~19.5us / ~high-20s / ~16us respectively); all alternative gather
// organizations (smem, shuffle, scratch pair/quad tables, padded rows)
// compute or measure worse. 4 samples/thread, per-sample scalar-LDG
// bilinear gather, float4 streaming I/O.

constexpr int B      = 32;
constexpr int S      = 524288;
constexpr int HOP    = 256;
constexpr int L      = 100;
constexpr int FRAMES = S / HOP;    // 2048
constexpr int TROWS  = FRAMES + 1; // 2049
constexpr int S4     = S / 4;      // 131072 float4 per batch row

__global__ __launch_bounds__(256)
void glottal_flow_kernel(const float* __restrict__ wp,
                         const float* __restrict__ tables,
                         float* __restrict__ out)
{
    int i4 = blockIdx.x * 256 + threadIdx.x;   // global float4 index
    int b  = i4 >> 17;                         // / S4 (131072)
    int s  = (i4 & (S4 - 1)) << 2;             // sample index within batch row
    int f  = s >> 8;                           // frame (HOP = 256)
    int t  = s & (HOP - 1);                    // position within frame

    float4 w = __ldcs(reinterpret_cast<const float4*>(wp) + i4);  // streaming

    const float* rowF = tables + (size_t)(b * TROWS + f) * L; // floor frame row
    const float* rowC = rowF + L;                              // ceil frame row

    float wk[4] = {w.x, w.y, w.z, w.w};
    float r[4];

#pragma unroll
    for (int k = 0; k < 4; ++k) {
        float idx_raw = wk[k] * (float)L;
        int   fi      = (int)idx_raw;              // trunc toward zero (data >= 0)
        fi            = max(0, min(fi, L - 1));    // clip like reference
        float p       = idx_raw - (float)fi;
        int   fj      = fi + 1;
        if (fj == L) fj = 0;                       // padded column L == column 0

        float loF = __ldg(rowF + fi);
        float hiF = __ldg(rowF + fj);
        float loC = __ldg(rowC + fi);
        float hiC = __ldg(rowC + fj);

        float vF = fmaf(p, hiF - loF, loF);        // phase lerp, floor frame
        float vC = fmaf(p, hiC - loC, loC);        // phase lerp, ceil frame
        float p2 = (float)(t + k) * (1.0f / (float)HOP);
        r[k] = fmaf(p2, vC - vF, vF);              // frame lerp
    }

    __stcs(reinterpret_cast<float4*>(out) + i4,    // streaming store
           make_float4(r[0], r[1], r[2], r[3]));
}

extern "C" void kernel_launch(void* const* d_in, const int* in_sizes, int n_in,
                              void* d_out, int out_size)
{
    const float* wp     = (const float*)d_in[0];
    const float* tables = (const float*)d_in[1];
    float*       out    = (float*)d_out;

    constexpr int total4 = (B * S) / 4;            // 4,194,304 float4 work items
    glottal_flow_kernel<<<total4 / 256, 256>>>(wp, tables, out);
}